// round 6
// baseline (speedup 1.0000x reference)
#include <cuda_runtime.h>
#include <cuda_fp16.h>
#include <cstdint>
#include <math.h>
#include <mma.h>

using namespace nvcuda;

#define B_  256
#define T_  128
#define X_  256
#define H_  1024

#define BM 64
#define BN 64
#define BK 32
#define STAGES 4
#define ALD 40                    // A smem row stride (halves)
#define BLD 72                    // B smem row stride (halves)
#define A_ST (BM * ALD)           // 2560 halves
#define B_ST (BK * BLD)           // 2304 halves
#define STAGE_HALVES (A_ST + B_ST)
#define DYN_SMEM (STAGES * STAGE_HALVES * 2)   // 38912 B (E reuse: 64*72*4=18432 ok)

#define NBLK 64                   // persistent grid size (<=148 SMs, 1 CTA/SM)

// ---------------- device scratch ----------------
__device__ float  g_y  [B_ * X_];
__device__ __half g_yh [B_ * X_];
__device__ __half g_h0 [B_ * H_];
__device__ __half g_h1 [B_ * H_];
#define WH_IN_OFF  0
#define WH_H_OFF   (X_ * H_)
#define WH_OUT_OFF (X_ * H_ + 3 * H_ * H_)
__device__ __half g_wh [X_ * H_ + 3 * H_ * H_ + H_ * X_];

// grid barrier state (zero-init at module load; count returns to 0 each barrier)
__device__ unsigned g_cnt;
__device__ unsigned g_gen;

#define CP16(dst, src) \
    asm volatile("cp.async.cg.shared.global [%0], [%1], 16;" :: "r"(dst), "l"(src))
#define CP_COMMIT() asm volatile("cp.async.commit_group;" ::: "memory")
#define CP_WAIT2()  asm volatile("cp.async.wait_group 2;" ::: "memory")

// ---------------- init / weight conversion ----------------
__global__ void node_init_kernel(const float* __restrict__ x, float* __restrict__ out) {
    int i = blockIdx.x * blockDim.x + threadIdx.x;
    float v = x[i];
    g_y[i]  = v;
    g_yh[i] = __float2half_rn(v);
    int b = i / X_, c = i % X_;
    out[(size_t)b * T_ * X_ + c] = v;
}

__global__ void cvt_kernel(const float* __restrict__ src, __half* __restrict__ dst, int n) {
    int i = blockIdx.x * blockDim.x + threadIdx.x;
    if (i < n) dst[i] = __float2half_rn(src[i]);
}

// ---------------- grid barrier (all NBLK CTAs co-resident) ----------------
__device__ __forceinline__ void gbar() {
    __syncthreads();
    if (threadIdx.x == 0) {
        unsigned gen = *(volatile unsigned*)&g_gen;
        __threadfence();                       // release my CTA's writes
        if (atomicAdd(&g_cnt, 1u) == NBLK - 1) {
            g_cnt = 0;
            __threadfence();
            *(volatile unsigned*)&g_gen = gen + 1;
        } else {
            while (*(volatile unsigned*)&g_gen == gen) { __nanosleep(64); }
            __threadfence();                   // acquire
        }
    }
    __syncthreads();
}

// ---------------- one BMxBN GEMM tile (WMMA fp16, fp32 acc) ----------------
// MODE 0: Cout(half) = tanh(z + bias)
// MODE 1: f = z + bias; y += dt*f; g_y/g_yh updated; out[:, t+1, :] = y
template <int MODE>
__device__ void do_tile(
    const __half* __restrict__ A, const __half* __restrict__ W,
    const float* __restrict__ bias, __half* __restrict__ Cout,
    int K, int N, int bm, int bn,
    float* gy, __half* gyh, float* out, const float* ts, int t,
    __half* smem)
{
    const int tid = threadIdx.x;
    const int w   = tid >> 5;
    const int wm  = w & 1;
    const int wn  = w >> 1;

    wmma::fragment<wmma::accumulator, 16, 16, 16, float> c[2][2];
    #pragma unroll
    for (int i = 0; i < 2; i++)
        #pragma unroll
        for (int j = 0; j < 2; j++)
            wmma::fill_fragment(c[i][j], 0.0f);

    const int NIT = K / BK;

    auto loadStage = [&](int it) {
        if (it < NIT) {
            const int k0 = it * BK;
            __half* As = smem + (it % STAGES) * STAGE_HALVES;
            __half* Bs = As + A_ST;
            uint32_t asb = (uint32_t)__cvta_generic_to_shared(As);
            uint32_t bsb = (uint32_t)__cvta_generic_to_shared(Bs);
            #pragma unroll
            for (int i = 0; i < 2; i++) {       // A: 64 rows x 32 halves
                int id = tid + i * 128;
                int r = id >> 2, c8 = id & 3;
                CP16(asb + (uint32_t)(r * ALD + c8 * 8) * 2,
                     A + (size_t)(bm + r) * K + k0 + c8 * 8);
            }
            #pragma unroll
            for (int i = 0; i < 2; i++) {       // B: 32 rows x 64 halves
                int id = tid + i * 128;
                int r = id >> 3, c8 = id & 7;
                CP16(bsb + (uint32_t)(r * BLD + c8 * 8) * 2,
                     W + (size_t)(k0 + r) * N + bn + c8 * 8);
            }
        }
        CP_COMMIT();
    };

    loadStage(0); loadStage(1); loadStage(2);

    for (int it = 0; it < NIT; it++) {
        CP_WAIT2();
        __syncthreads();

        const __half* Ab = smem + (it % STAGES) * STAGE_HALVES;
        const __half* Bb = Ab + A_ST;

        #pragma unroll
        for (int kf = 0; kf < BK / 16; kf++) {
            wmma::fragment<wmma::matrix_a, 16, 16, 16, __half, wmma::row_major> a0, a1;
            wmma::fragment<wmma::matrix_b, 16, 16, 16, __half, wmma::row_major> b0, b1;
            wmma::load_matrix_sync(a0, Ab + (wm * 32 +  0) * ALD + kf * 16, ALD);
            wmma::load_matrix_sync(a1, Ab + (wm * 32 + 16) * ALD + kf * 16, ALD);
            wmma::load_matrix_sync(b0, Bb + (kf * 16) * BLD + wn * 32 +  0, BLD);
            wmma::load_matrix_sync(b1, Bb + (kf * 16) * BLD + wn * 32 + 16, BLD);
            wmma::mma_sync(c[0][0], a0, b0, c[0][0]);
            wmma::mma_sync(c[0][1], a0, b1, c[0][1]);
            wmma::mma_sync(c[1][0], a1, b0, c[1][0]);
            wmma::mma_sync(c[1][1], a1, b1, c[1][1]);
        }
        loadStage(it + 3);
    }

    // ---- epilogue ----
    __syncthreads();
    float* E = reinterpret_cast<float*>(smem);   // [64][72] fp32
    #pragma unroll
    for (int i = 0; i < 2; i++)
        #pragma unroll
        for (int j = 0; j < 2; j++)
            wmma::store_matrix_sync(E + (size_t)(wm * 32 + i * 16) * BLD + wn * 32 + j * 16,
                                    c[i][j], BLD, wmma::mem_row_major);
    __syncthreads();

    const int r     = tid >> 1;
    const int cbase = (tid & 1) * 32;

    if (MODE == 0) {
        #pragma unroll
        for (int j = 0; j < 8; j++) {
            int col = cbase + j * 4;
            float4 v = *reinterpret_cast<float4*>(&E[r * BLD + col]);
            __half2 p0 = __halves2half2(__float2half_rn(tanhf(v.x + bias[bn + col + 0])),
                                        __float2half_rn(tanhf(v.y + bias[bn + col + 1])));
            __half2 p1 = __halves2half2(__float2half_rn(tanhf(v.z + bias[bn + col + 2])),
                                        __float2half_rn(tanhf(v.w + bias[bn + col + 3])));
            uint2 pk = make_uint2(*reinterpret_cast<uint32_t*>(&p0),
                                  *reinterpret_cast<uint32_t*>(&p1));
            *reinterpret_cast<uint2*>(&Cout[(size_t)(bm + r) * N + bn + col]) = pk;
        }
    } else {
        const float dt = ts[t + 1] - ts[t];
        #pragma unroll
        for (int j = 0; j < 8; j++) {
            int col = cbase + j * 4;
            int idx = (bm + r) * X_ + bn + col;
            float4 yv = *reinterpret_cast<float4*>(&gy[idx]);
            yv.x += dt * (E[r * BLD + col + 0] + bias[bn + col + 0]);
            yv.y += dt * (E[r * BLD + col + 1] + bias[bn + col + 1]);
            yv.z += dt * (E[r * BLD + col + 2] + bias[bn + col + 2]);
            yv.w += dt * (E[r * BLD + col + 3] + bias[bn + col + 3]);
            *reinterpret_cast<float4*>(&gy[idx]) = yv;
            __half2 p0 = __halves2half2(__float2half_rn(yv.x), __float2half_rn(yv.y));
            __half2 p1 = __halves2half2(__float2half_rn(yv.z), __float2half_rn(yv.w));
            uint2 pk = make_uint2(*reinterpret_cast<uint32_t*>(&p0),
                                  *reinterpret_cast<uint32_t*>(&p1));
            *reinterpret_cast<uint2*>(&gyh[idx]) = pk;
            *reinterpret_cast<float4*>(&out[(size_t)(bm + r) * T_ * X_ +
                                            (size_t)(t + 1) * X_ + bn + col]) = yv;
        }
    }
}

// ---------------- persistent kernel: all 127 steps ----------------
__global__ void __launch_bounds__(128, 1) node_persistent(
    const __half* __restrict__ Wh_in, const __half* __restrict__ Wh_h,
    const __half* __restrict__ Wh_out,
    const float* __restrict__ b_in, const float* __restrict__ b_h,
    const float* __restrict__ b_out,
    float* __restrict__ gy, __half* __restrict__ gyh,
    __half* __restrict__ h0, __half* __restrict__ h1,
    float* __restrict__ out, const float* __restrict__ ts)
{
    extern __shared__ __half smem[];
    const int c = blockIdx.x;                 // 0..63
    const int bmH = (c >> 4) * BM;            // hidden/in tiling: 4 x 16
    const int bnH = (c & 15) * BN;

    for (int t = 0; t < T_ - 1; t++) {
        do_tile<0>(gyh, Wh_in, b_in, h0, X_, H_, bmH, bnH,
                   nullptr, nullptr, nullptr, nullptr, 0, smem);
        gbar();
        do_tile<0>(h0, Wh_h + 0 * H_ * H_, b_h + 0 * H_, h1, H_, H_, bmH, bnH,
                   nullptr, nullptr, nullptr, nullptr, 0, smem);
        gbar();
        do_tile<0>(h1, Wh_h + 1 * H_ * H_, b_h + 1 * H_, h0, H_, H_, bmH, bnH,
                   nullptr, nullptr, nullptr, nullptr, 0, smem);
        gbar();
        do_tile<0>(h0, Wh_h + 2 * H_ * H_, b_h + 2 * H_, h1, H_, H_, bmH, bnH,
                   nullptr, nullptr, nullptr, nullptr, 0, smem);
        gbar();
        if (c < 16) {
            do_tile<1>(h1, Wh_out, b_out, nullptr, H_, X_,
                       (c >> 2) * BM, (c & 3) * BN,
                       gy, gyh, out, ts, t, smem);
        }
        gbar();
    }
}

// ---------------- host ----------------
extern "C" void kernel_launch(void* const* d_in, const int* in_sizes, int n_in,
                              void* d_out, int out_size)
{
    const float* x     = (const float*)d_in[0];
    const float* ts    = (const float*)d_in[1];
    const float* W_in  = (const float*)d_in[2];
    const float* b_in  = (const float*)d_in[3];
    const float* W_h   = (const float*)d_in[4];
    const float* b_h   = (const float*)d_in[5];
    const float* W_out = (const float*)d_in[6];
    const float* b_out = (const float*)d_in[7];
    float* out = (float*)d_out;

    float  *py;
    __half *pyh, *ph0, *ph1, *pwh;
    cudaGetSymbolAddress((void**)&py,  g_y);
    cudaGetSymbolAddress((void**)&pyh, g_yh);
    cudaGetSymbolAddress((void**)&ph0, g_h0);
    cudaGetSymbolAddress((void**)&ph1, g_h1);
    cudaGetSymbolAddress((void**)&pwh, g_wh);

    cudaFuncSetAttribute(node_persistent, cudaFuncAttributeMaxDynamicSharedMemorySize, DYN_SMEM);

    cvt_kernel<<<(X_ * H_ + 255) / 256, 256>>>(W_in,  pwh + WH_IN_OFF,  X_ * H_);
    cvt_kernel<<<(3 * H_ * H_ + 255) / 256, 256>>>(W_h, pwh + WH_H_OFF, 3 * H_ * H_);
    cvt_kernel<<<(H_ * X_ + 255) / 256, 256>>>(W_out, pwh + WH_OUT_OFF, H_ * X_);

    node_init_kernel<<<(B_ * X_) / 256, 256>>>(x, out);

    node_persistent<<<NBLK, 128, DYN_SMEM>>>(
        pwh + WH_IN_OFF, pwh + WH_H_OFF, pwh + WH_OUT_OFF,
        b_in, b_h, b_out,
        py, pyh, ph0, ph1, out, ts);
}

// round 7
// speedup vs baseline: 1.3075x; 1.3075x over previous
#include <cuda_runtime.h>
#include <cuda_fp16.h>
#include <cstdint>
#include <math.h>
#include <mma.h>

using namespace nvcuda;

#define B_  256
#define T_  128
#define X_  256
#define H_  1024

#define BM 64
#define BN 64
#define BK 32
#define STAGES 4
#define ALD 40                    // A smem row stride (halves)
#define BLD 72                    // B smem row stride (halves)
#define A_ST (BM * ALD)           // 2560 halves
#define B_ST (BK * BLD)           // 2304 halves
#define STAGE_HALVES (A_ST + B_ST)
#define DYN_SMEM (STAGES * STAGE_HALVES * 2)   // 38912 B (epilogue E: 64*72*4=18432 ok)

// ---------------- device scratch ----------------
__device__ float  g_y  [B_ * X_];   // fp32 Euler state
__device__ __half g_yh [B_ * X_];   // fp16 copy (GEMM A operand)
__device__ __half g_h0 [B_ * H_];
__device__ __half g_h1 [B_ * H_];
#define WH_IN_OFF  0
#define WH_H_OFF   (X_ * H_)
#define WH_OUT_OFF (X_ * H_ + 3 * H_ * H_)
__device__ __half g_wh [X_ * H_ + 3 * H_ * H_ + H_ * X_];

#define CP16(dst, src) \
    asm volatile("cp.async.cg.shared.global [%0], [%1], 16;" :: "r"(dst), "l"(src))
#define CP_COMMIT() asm volatile("cp.async.commit_group;" ::: "memory")
#define CP_WAIT2()  asm volatile("cp.async.wait_group 2;" ::: "memory")

// ---------------- init / weight conversion ----------------
__global__ void node_init_kernel(const float* __restrict__ x, float* __restrict__ out) {
    int i = blockIdx.x * blockDim.x + threadIdx.x;
    float v = x[i];
    g_y[i]  = v;
    g_yh[i] = __float2half_rn(v);
    int b = i / X_, c = i % X_;
    out[(size_t)b * T_ * X_ + c] = v;
}

__global__ void cvt_kernel(const float* __restrict__ src, __half* __restrict__ dst, int n) {
    int i = blockIdx.x * blockDim.x + threadIdx.x;
    if (i < n) dst[i] = __float2half_rn(src[i]);
}

// ---------------- WMMA fp16 GEMM, fp32 accum, 4-stage cp.async, 8 warps ----------------
// C[256, N] = A[256, K] @ W[K, N] (+bias, +epilogue)
// MODE 0: Cout(half) = tanh(z + bias)
// MODE 1: f = z + bias; y += dt*f; update g_y/g_yh; out[:, t+1, :] = y
template <int MODE>
__global__ void __launch_bounds__(256, 1) gemm_wmma(
    const __half* __restrict__ A, const __half* __restrict__ W,
    const float* __restrict__ bias, __half* __restrict__ Cout,
    int K, int N,
    float* __restrict__ gy, __half* __restrict__ gyh,
    float* __restrict__ out, const float* __restrict__ ts, int t)
{
    extern __shared__ __half smem[];

    const int tid = threadIdx.x;          // 0..255
    const int bm  = blockIdx.y * BM;
    const int bn  = blockIdx.x * BN;
    const int w   = tid >> 5;             // 0..7
    const int wm  = w & 3;                // 4 m-rows of 16
    const int wn  = w >> 2;               // 2 n-cols of 32

    wmma::fragment<wmma::accumulator, 16, 16, 16, float> c0, c1;
    wmma::fill_fragment(c0, 0.0f);
    wmma::fill_fragment(c1, 0.0f);

    const int NIT = K / BK;

    auto loadStage = [&](int it) {
        if (it < NIT) {
            const int k0 = it * BK;
            __half* As = smem + (it % STAGES) * STAGE_HALVES;
            __half* Bs = As + A_ST;
            uint32_t asb = (uint32_t)__cvta_generic_to_shared(As);
            uint32_t bsb = (uint32_t)__cvta_generic_to_shared(Bs);
            {   // A: 64 rows x 32 halves = 256 x 16B, one per thread
                int r = tid >> 2, c8 = tid & 3;
                CP16(asb + (uint32_t)(r * ALD + c8 * 8) * 2,
                     A + (size_t)(bm + r) * K + k0 + c8 * 8);
            }
            {   // B: 32 rows x 64 halves = 256 x 16B, one per thread
                int r = tid >> 3, c8 = tid & 7;
                CP16(bsb + (uint32_t)(r * BLD + c8 * 8) * 2,
                     W + (size_t)(k0 + r) * N + bn + c8 * 8);
            }
        }
        CP_COMMIT();
    };

    loadStage(0); loadStage(1); loadStage(2);

    for (int it = 0; it < NIT; it++) {
        CP_WAIT2();
        __syncthreads();

        const __half* Ab = smem + (it % STAGES) * STAGE_HALVES;
        const __half* Bb = Ab + A_ST;

        #pragma unroll
        for (int kf = 0; kf < BK / 16; kf++) {
            wmma::fragment<wmma::matrix_a, 16, 16, 16, __half, wmma::row_major> a0;
            wmma::fragment<wmma::matrix_b, 16, 16, 16, __half, wmma::row_major> b0, b1;
            wmma::load_matrix_sync(a0, Ab + (wm * 16) * ALD + kf * 16, ALD);
            wmma::load_matrix_sync(b0, Bb + (kf * 16) * BLD + wn * 32 +  0, BLD);
            wmma::load_matrix_sync(b1, Bb + (kf * 16) * BLD + wn * 32 + 16, BLD);
            wmma::mma_sync(c0, a0, b0, c0);
            wmma::mma_sync(c1, a0, b1, c1);
        }
        loadStage(it + 3);
    }

    // ---- epilogue: accumulators -> smem(fp32) -> elementwise ----
    __syncthreads();
    float* E = reinterpret_cast<float*>(smem);   // [64][72] fp32 = 18432 B
    wmma::store_matrix_sync(E + (size_t)(wm * 16) * BLD + wn * 32 +  0, c0, BLD, wmma::mem_row_major);
    wmma::store_matrix_sync(E + (size_t)(wm * 16) * BLD + wn * 32 + 16, c1, BLD, wmma::mem_row_major);
    __syncthreads();

    const int r     = tid >> 2;           // 0..63
    const int cbase = (tid & 3) * 16;     // 0/16/32/48

    if (MODE == 0) {
        #pragma unroll
        for (int j = 0; j < 4; j++) {
            int col = cbase + j * 4;
            float4 v = *reinterpret_cast<float4*>(&E[r * BLD + col]);
            __half2 p0 = __halves2half2(__float2half_rn(tanhf(v.x + bias[bn + col + 0])),
                                        __float2half_rn(tanhf(v.y + bias[bn + col + 1])));
            __half2 p1 = __halves2half2(__float2half_rn(tanhf(v.z + bias[bn + col + 2])),
                                        __float2half_rn(tanhf(v.w + bias[bn + col + 3])));
            uint2 pk = make_uint2(*reinterpret_cast<uint32_t*>(&p0),
                                  *reinterpret_cast<uint32_t*>(&p1));
            *reinterpret_cast<uint2*>(&Cout[(size_t)(bm + r) * N + bn + col]) = pk;
        }
    } else {
        const float dt = ts[t + 1] - ts[t];
        #pragma unroll
        for (int j = 0; j < 4; j++) {
            int col = cbase + j * 4;
            int idx = (bm + r) * X_ + bn + col;
            float4 yv = *reinterpret_cast<float4*>(&gy[idx]);
            yv.x += dt * (E[r * BLD + col + 0] + bias[bn + col + 0]);
            yv.y += dt * (E[r * BLD + col + 1] + bias[bn + col + 1]);
            yv.z += dt * (E[r * BLD + col + 2] + bias[bn + col + 2]);
            yv.w += dt * (E[r * BLD + col + 3] + bias[bn + col + 3]);
            *reinterpret_cast<float4*>(&gy[idx]) = yv;
            __half2 p0 = __halves2half2(__float2half_rn(yv.x), __float2half_rn(yv.y));
            __half2 p1 = __halves2half2(__float2half_rn(yv.z), __float2half_rn(yv.w));
            uint2 pk = make_uint2(*reinterpret_cast<uint32_t*>(&p0),
                                  *reinterpret_cast<uint32_t*>(&p1));
            *reinterpret_cast<uint2*>(&gyh[idx]) = pk;
            *reinterpret_cast<float4*>(&out[(size_t)(bm + r) * T_ * X_ +
                                            (size_t)(t + 1) * X_ + bn + col]) = yv;
        }
    }
}

// ---------------- host ----------------
extern "C" void kernel_launch(void* const* d_in, const int* in_sizes, int n_in,
                              void* d_out, int out_size)
{
    const float* x     = (const float*)d_in[0];
    const float* ts    = (const float*)d_in[1];
    const float* W_in  = (const float*)d_in[2];
    const float* b_in  = (const float*)d_in[3];
    const float* W_h   = (const float*)d_in[4];
    const float* b_h   = (const float*)d_in[5];
    const float* W_out = (const float*)d_in[6];
    const float* b_out = (const float*)d_in[7];
    float* out = (float*)d_out;

    float  *py;
    __half *pyh, *ph0, *ph1, *pwh;
    cudaGetSymbolAddress((void**)&py,  g_y);
    cudaGetSymbolAddress((void**)&pyh, g_yh);
    cudaGetSymbolAddress((void**)&ph0, g_h0);
    cudaGetSymbolAddress((void**)&ph1, g_h1);
    cudaGetSymbolAddress((void**)&pwh, g_wh);

    cudaFuncSetAttribute(gemm_wmma<0>, cudaFuncAttributeMaxDynamicSharedMemorySize, DYN_SMEM);
    cudaFuncSetAttribute(gemm_wmma<1>, cudaFuncAttributeMaxDynamicSharedMemorySize, DYN_SMEM);

    cvt_kernel<<<(X_ * H_ + 255) / 256, 256>>>(W_in,  pwh + WH_IN_OFF,  X_ * H_);
    cvt_kernel<<<(3 * H_ * H_ + 255) / 256, 256>>>(W_h, pwh + WH_H_OFF, 3 * H_ * H_);
    cvt_kernel<<<(H_ * X_ + 255) / 256, 256>>>(W_out, pwh + WH_OUT_OFF, H_ * X_);

    node_init_kernel<<<(B_ * X_) / 256, 256>>>(x, out);

    dim3 blk(256);
    dim3 gridH(H_ / BN, B_ / BM);   // (16, 4) = 64 CTAs
    dim3 gridO(X_ / BN, B_ / BM);   // (4, 4)  = 16 CTAs

    const __half* Wh_in  = pwh + WH_IN_OFF;
    const __half* Wh_h   = pwh + WH_H_OFF;
    const __half* Wh_out = pwh + WH_OUT_OFF;

    for (int t = 0; t < T_ - 1; t++) {
        gemm_wmma<0><<<gridH, blk, DYN_SMEM>>>(pyh, Wh_in,          b_in,       ph0, X_, H_, nullptr, nullptr, nullptr, nullptr, 0);
        gemm_wmma<0><<<gridH, blk, DYN_SMEM>>>(ph0, Wh_h + 0*H_*H_, b_h + 0*H_, ph1, H_, H_, nullptr, nullptr, nullptr, nullptr, 0);
        gemm_wmma<0><<<gridH, blk, DYN_SMEM>>>(ph1, Wh_h + 1*H_*H_, b_h + 1*H_, ph0, H_, H_, nullptr, nullptr, nullptr, nullptr, 0);
        gemm_wmma<0><<<gridH, blk, DYN_SMEM>>>(ph0, Wh_h + 2*H_*H_, b_h + 2*H_, ph1, H_, H_, nullptr, nullptr, nullptr, nullptr, 0);
        gemm_wmma<1><<<gridO, blk, DYN_SMEM>>>(ph1, Wh_out,         b_out, nullptr, H_, X_, py, pyh, out, ts, t);
    }
}

// round 8
// speedup vs baseline: 1.4812x; 1.1329x over previous
#include <cuda_runtime.h>
#include <cuda_fp16.h>
#include <cstdint>
#include <math.h>
#include <mma.h>

using namespace nvcuda;

#define B_  256
#define T_  128
#define X_  256
#define H_  1024

#define BM 32
#define BN 64
#define BK 32
#define STAGES 4
#define ALD 40                    // A smem row stride (halves)
#define BLD 72                    // B smem row stride (halves)
#define A_ST (BM * ALD)           // 1280 halves
#define B_ST (BK * BLD)           // 2304 halves
#define STAGE_HALVES (A_ST + B_ST)
#define DYN_SMEM (STAGES * STAGE_HALVES * 2)   // 28672 B (epilogue E: 32*72*4 = 9216 ok)

// ---------------- device scratch ----------------
__device__ float  g_y  [B_ * X_];   // fp32 Euler state
__device__ __half g_yh [B_ * X_];   // fp16 copy (GEMM A operand)
__device__ __half g_h0 [B_ * H_];
__device__ __half g_h1 [B_ * H_];
#define WH_IN_OFF  0
#define WH_H_OFF   (X_ * H_)
#define WH_OUT_OFF (X_ * H_ + 3 * H_ * H_)
__device__ __half g_wh [X_ * H_ + 3 * H_ * H_ + H_ * X_];

#define CP16(dst, src) \
    asm volatile("cp.async.cg.shared.global [%0], [%1], 16;" :: "r"(dst), "l"(src))
#define CP_COMMIT() asm volatile("cp.async.commit_group;" ::: "memory")
#define CP_WAIT2()  asm volatile("cp.async.wait_group 2;" ::: "memory")

// ---------------- init / weight conversion ----------------
__global__ void node_init_kernel(const float* __restrict__ x, float* __restrict__ out) {
    int i = blockIdx.x * blockDim.x + threadIdx.x;
    float v = x[i];
    g_y[i]  = v;
    g_yh[i] = __float2half_rn(v);
    int b = i / X_, c = i % X_;
    out[(size_t)b * T_ * X_ + c] = v;
}

__global__ void cvt_kernel(const float* __restrict__ src, __half* __restrict__ dst, int n) {
    int i = blockIdx.x * blockDim.x + threadIdx.x;
    if (i < n) dst[i] = __float2half_rn(src[i]);
}

// ---------------- WMMA fp16 GEMM: 32x64 CTA tile, 8 warps of 16x16 ----------------
// C[256, N] = A[256, K] @ W[K, N] (+bias, +epilogue)
// MODE 0: Cout(half) = tanh(z + bias)
// MODE 1: f = z + bias; y += dt*f; update g_y/g_yh; out[:, t+1, :] = y
template <int MODE>
__global__ void __launch_bounds__(256, 1) gemm_wmma(
    const __half* __restrict__ A, const __half* __restrict__ W,
    const float* __restrict__ bias, __half* __restrict__ Cout,
    int K, int N,
    float* __restrict__ gy, __half* __restrict__ gyh,
    float* __restrict__ out, const float* __restrict__ ts, int t)
{
    extern __shared__ __half smem[];

    const int tid = threadIdx.x;          // 0..255
    const int bm  = blockIdx.y * BM;
    const int bn  = blockIdx.x * BN;
    const int w   = tid >> 5;             // 0..7
    const int wm  = w & 1;                // 2 m-rows of 16
    const int wn  = w >> 1;               // 4 n-cols of 16

    wmma::fragment<wmma::accumulator, 16, 16, 16, float> c0;
    wmma::fill_fragment(c0, 0.0f);

    const int NIT = K / BK;

    auto loadStage = [&](int it) {
        if (it < NIT) {
            const int k0 = it * BK;
            __half* As = smem + (it % STAGES) * STAGE_HALVES;
            __half* Bs = As + A_ST;
            uint32_t asb = (uint32_t)__cvta_generic_to_shared(As);
            uint32_t bsb = (uint32_t)__cvta_generic_to_shared(Bs);
            if (tid < 128) {   // A: 32 rows x 32 halves = 128 x 16B
                int r = tid >> 2, c8 = tid & 3;
                CP16(asb + (uint32_t)(r * ALD + c8 * 8) * 2,
                     A + (size_t)(bm + r) * K + k0 + c8 * 8);
            }
            {   // B: 32 rows x 64 halves = 256 x 16B, one per thread
                int r = tid >> 3, c8 = tid & 7;
                CP16(bsb + (uint32_t)(r * BLD + c8 * 8) * 2,
                     W + (size_t)(k0 + r) * N + bn + c8 * 8);
            }
        }
        CP_COMMIT();
    };

    loadStage(0); loadStage(1); loadStage(2);

    for (int it = 0; it < NIT; it++) {
        CP_WAIT2();
        __syncthreads();

        const __half* Ab = smem + (it % STAGES) * STAGE_HALVES;
        const __half* Bb = Ab + A_ST;

        #pragma unroll
        for (int kf = 0; kf < BK / 16; kf++) {
            wmma::fragment<wmma::matrix_a, 16, 16, 16, __half, wmma::row_major> a0;
            wmma::fragment<wmma::matrix_b, 16, 16, 16, __half, wmma::row_major> b0;
            wmma::load_matrix_sync(a0, Ab + (wm * 16) * ALD + kf * 16, ALD);
            wmma::load_matrix_sync(b0, Bb + (kf * 16) * BLD + wn * 16, BLD);
            wmma::mma_sync(c0, a0, b0, c0);
        }
        loadStage(it + 3);
    }

    // ---- epilogue: accumulators -> smem(fp32) -> elementwise ----
    __syncthreads();
    float* E = reinterpret_cast<float*>(smem);   // [32][72] fp32 = 9216 B
    wmma::store_matrix_sync(E + (size_t)(wm * 16) * BLD + wn * 16, c0, BLD, wmma::mem_row_major);
    __syncthreads();

    const int r     = tid >> 3;           // 0..31
    const int cbase = (tid & 7) * 8;      // 0..56 step 8

    if (MODE == 0) {
        #pragma unroll
        for (int j = 0; j < 2; j++) {
            int col = cbase + j * 4;
            float4 v = *reinterpret_cast<float4*>(&E[r * BLD + col]);
            __half2 p0 = __halves2half2(__float2half_rn(tanhf(v.x + bias[bn + col + 0])),
                                        __float2half_rn(tanhf(v.y + bias[bn + col + 1])));
            __half2 p1 = __halves2half2(__float2half_rn(tanhf(v.z + bias[bn + col + 2])),
                                        __float2half_rn(tanhf(v.w + bias[bn + col + 3])));
            uint2 pk = make_uint2(*reinterpret_cast<uint32_t*>(&p0),
                                  *reinterpret_cast<uint32_t*>(&p1));
            *reinterpret_cast<uint2*>(&Cout[(size_t)(bm + r) * N + bn + col]) = pk;
        }
    } else {
        const float dt = ts[t + 1] - ts[t];
        #pragma unroll
        for (int j = 0; j < 2; j++) {
            int col = cbase + j * 4;
            int idx = (bm + r) * X_ + bn + col;
            float4 yv = *reinterpret_cast<float4*>(&gy[idx]);
            yv.x += dt * (E[r * BLD + col + 0] + bias[bn + col + 0]);
            yv.y += dt * (E[r * BLD + col + 1] + bias[bn + col + 1]);
            yv.z += dt * (E[r * BLD + col + 2] + bias[bn + col + 2]);
            yv.w += dt * (E[r * BLD + col + 3] + bias[bn + col + 3]);
            *reinterpret_cast<float4*>(&gy[idx]) = yv;
            __half2 p0 = __halves2half2(__float2half_rn(yv.x), __float2half_rn(yv.y));
            __half2 p1 = __halves2half2(__float2half_rn(yv.z), __float2half_rn(yv.w));
            uint2 pk = make_uint2(*reinterpret_cast<uint32_t*>(&p0),
                                  *reinterpret_cast<uint32_t*>(&p1));
            *reinterpret_cast<uint2*>(&gyh[idx]) = pk;
            *reinterpret_cast<float4*>(&out[(size_t)(bm + r) * T_ * X_ +
                                            (size_t)(t + 1) * X_ + bn + col]) = yv;
        }
    }
}

// ---------------- host ----------------
extern "C" void kernel_launch(void* const* d_in, const int* in_sizes, int n_in,
                              void* d_out, int out_size)
{
    const float* x     = (const float*)d_in[0];
    const float* ts    = (const float*)d_in[1];
    const float* W_in  = (const float*)d_in[2];
    const float* b_in  = (const float*)d_in[3];
    const float* W_h   = (const float*)d_in[4];
    const float* b_h   = (const float*)d_in[5];
    const float* W_out = (const float*)d_in[6];
    const float* b_out = (const float*)d_in[7];
    float* out = (float*)d_out;

    float  *py;
    __half *pyh, *ph0, *ph1, *pwh;
    cudaGetSymbolAddress((void**)&py,  g_y);
    cudaGetSymbolAddress((void**)&pyh, g_yh);
    cudaGetSymbolAddress((void**)&ph0, g_h0);
    cudaGetSymbolAddress((void**)&ph1, g_h1);
    cudaGetSymbolAddress((void**)&pwh, g_wh);

    cudaFuncSetAttribute(gemm_wmma<0>, cudaFuncAttributeMaxDynamicSharedMemorySize, DYN_SMEM);
    cudaFuncSetAttribute(gemm_wmma<1>, cudaFuncAttributeMaxDynamicSharedMemorySize, DYN_SMEM);

    cvt_kernel<<<(X_ * H_ + 255) / 256, 256>>>(W_in,  pwh + WH_IN_OFF,  X_ * H_);
    cvt_kernel<<<(3 * H_ * H_ + 255) / 256, 256>>>(W_h, pwh + WH_H_OFF, 3 * H_ * H_);
    cvt_kernel<<<(H_ * X_ + 255) / 256, 256>>>(W_out, pwh + WH_OUT_OFF, H_ * X_);

    node_init_kernel<<<(B_ * X_) / 256, 256>>>(x, out);

    dim3 blk(256);
    dim3 gridH(H_ / BN, B_ / BM);   // (16, 8) = 128 CTAs
    dim3 gridO(X_ / BN, B_ / BM);   // (4, 8)  = 32 CTAs

    const __half* Wh_in  = pwh + WH_IN_OFF;
    const __half* Wh_h   = pwh + WH_H_OFF;
    const __half* Wh_out = pwh + WH_OUT_OFF;

    for (int t = 0; t < T_ - 1; t++) {
        gemm_wmma<0><<<gridH, blk, DYN_SMEM>>>(pyh, Wh_in,          b_in,       ph0, X_, H_, nullptr, nullptr, nullptr, nullptr, 0);
        gemm_wmma<0><<<gridH, blk, DYN_SMEM>>>(ph0, Wh_h + 0*H_*H_, b_h + 0*H_, ph1, H_, H_, nullptr, nullptr, nullptr, nullptr, 0);
        gemm_wmma<0><<<gridH, blk, DYN_SMEM>>>(ph1, Wh_h + 1*H_*H_, b_h + 1*H_, ph0, H_, H_, nullptr, nullptr, nullptr, nullptr, 0);
        gemm_wmma<0><<<gridH, blk, DYN_SMEM>>>(ph0, Wh_h + 2*H_*H_, b_h + 2*H_, ph1, H_, H_, nullptr, nullptr, nullptr, nullptr, 0);
        gemm_wmma<1><<<gridO, blk, DYN_SMEM>>>(ph1, Wh_out,         b_out, nullptr, H_, X_, py, pyh, out, ts, t);
    }
}